// round 4
// baseline (speedup 1.0000x reference)
#include <cuda_runtime.h>
#include <cstdint>

#define NN 100000
#define NE 1600000
#define NG 256
#define D  128
#define DOUT 64

// ---------------- scratch (static device globals; no allocs) ----------------
__device__ __align__(16) float g_h1[(size_t)NN * D];
__device__ __align__(16) float g_h2[(size_t)NN * D];
__device__ __align__(16) float g_agg[(size_t)NN * D];
__device__ __align__(16) int   g_rowoff[NN + 1];
__device__ __align__(16) int   g_cursor[NN];
__device__ __align__(16) int   g_count[NN];
__device__ __align__(16) int   g_csr[NE];
__device__ __align__(16) float g_deginv[NN];
__device__ __align__(16) float g_pool[NG * 2 * D];   // [g][0:128]=aggmean, [128:256]=hmean
__device__ __align__(16) int   g_gstart[NG + 1];

// ---------------- init: zero edge counters ----------------
__global__ void k_init() {
    int i = blockIdx.x * blockDim.x + threadIdx.x;
    if (i < NN) g_count[i] = 0;
}

// ---------------- in-degree histogram over dst ----------------
__global__ void k_hist(const int* __restrict__ ei) {
    int e = blockIdx.x * blockDim.x + threadIdx.x;
    if (e < NE) {
        int d = ei[NE + e];
        atomicAdd(&g_count[d], 1);
    }
}

// ---------------- single-block exclusive scan -> rowoff/cursor/deginv -------
__global__ void k_scan() {
    const int CH = 98;                 // 1024*98 >= 100000
    __shared__ int sc[1024];
    int t = threadIdx.x;
    int base = t * CH;
    int s = 0;
    for (int i = 0; i < CH; i++) {
        int idx = base + i;
        if (idx < NN) s += g_count[idx];
    }
    sc[t] = s;
    __syncthreads();
    for (int off = 1; off < 1024; off <<= 1) {
        int v = (t >= off) ? sc[t - off] : 0;
        __syncthreads();
        sc[t] += v;
        __syncthreads();
    }
    int run = sc[t] - s;               // exclusive prefix
    for (int i = 0; i < CH; i++) {
        int idx = base + i;
        if (idx < NN) {
            int c = g_count[idx];
            g_rowoff[idx] = run;
            g_cursor[idx] = run;
            g_deginv[idx] = 1.0f / (float)max(c, 1);
            run += c;
        }
    }
    if (t == 1023) g_rowoff[NN] = sc[1023];
}

// ---------------- CSR fill (src list grouped by dst) ----------------
__global__ void k_fill(const int* __restrict__ ei) {
    int e = blockIdx.x * blockDim.x + threadIdx.x;
    if (e < NE) {
        int s = ei[e];
        int d = ei[NE + e];
        int pos = atomicAdd(&g_cursor[d], 1);
        g_csr[pos] = s;
    }
}

// ---------------- graph boundaries: batch is sorted ----------------
// g_gstart[g] = first node index with batch[node] >= g (binary search).
__global__ void k_gbounds(const int* __restrict__ batch) {
    int g = threadIdx.x;
    if (g > NG) return;
    int lo = 0, hi = NN;
    while (lo < hi) {
        int mid = (lo + hi) >> 1;
        if (batch[mid] < g) lo = mid + 1; else hi = mid;
    }
    g_gstart[g] = lo;
}

// ---------------- gather-mean aggregation: one warp per node ----------------
__global__ void k_agg(const float* __restrict__ hin) {
    int node = (blockIdx.x * blockDim.x + threadIdx.x) >> 5;
    if (node >= NN) return;
    int lane = threadIdx.x & 31;
    int beg = g_rowoff[node], end = g_rowoff[node + 1];
    float4 acc = make_float4(0.f, 0.f, 0.f, 0.f);
    for (int e = beg; e < end; e++) {
        int s = g_csr[e];
        float4 v = *(const float4*)(hin + (size_t)s * D + lane * 4);
        acc.x += v.x; acc.y += v.y; acc.z += v.z; acc.w += v.w;
    }
    float sc = g_deginv[node];
    acc.x *= sc; acc.y *= sc; acc.z *= sc; acc.w *= sc;
    *(float4*)(g_agg + (size_t)node * D + lane * 4) = acc;
}

// ---------------- fused GEMM: hout = act(agg@Wrel + hin@Wroot + b) ----------
// 128x128 block tile, K=256 (first half agg/Wrel, second half hin/Wroot),
// BK=16, 256 threads, 8x8 per-thread microtile.
__global__ __launch_bounds__(256) void k_gemm(
    const float* __restrict__ A0,    // agg (scaled), k in [0,128)
    const float* __restrict__ A1,    // hin,          k in [128,256)
    const float* __restrict__ Wrel,
    const float* __restrict__ Wroot,
    const float* __restrict__ bias,
    float* __restrict__ hout,
    int doRelu)
{
    __shared__ float As[16][132];    // [k][row], padded
    __shared__ float Bs[16][128];    // [k][n]
    int row0 = blockIdx.x * 128;
    int tid = threadIdx.x;
    int tr = tid >> 4, tc = tid & 15;
    int rB = tr * 8, cB = tc * 8;

    float acc[8][8];
#pragma unroll
    for (int i = 0; i < 8; i++)
#pragma unroll
        for (int j = 0; j < 8; j++) acc[i][j] = 0.f;

#pragma unroll 1
    for (int kt = 0; kt < 16; kt++) {
        int k0 = kt * 16;
        const float* src = (k0 < 128) ? A0 : A1;
        const float* W   = (k0 < 128) ? Wrel : Wroot;
        int kc = k0 & 127;

        // load A tile (128 rows x 16 k), store transposed into smem
#pragma unroll
        for (int i = 0; i < 2; i++) {
            int slot = tid * 2 + i;                 // 0..511
            int r = slot >> 2;
            int c4 = (slot & 3) * 4;
            float4 v = make_float4(0.f, 0.f, 0.f, 0.f);
            int grow = row0 + r;
            if (grow < NN)
                v = *(const float4*)(src + (size_t)grow * D + kc + c4);
            As[c4 + 0][r] = v.x;
            As[c4 + 1][r] = v.y;
            As[c4 + 2][r] = v.z;
            As[c4 + 3][r] = v.w;
        }
        // load B tile (16 k x 128 n)
#pragma unroll
        for (int i = 0; i < 2; i++) {
            int slot = tid * 2 + i;                 // 0..511
            int kk = slot >> 5;
            int n4 = (slot & 31) * 4;
            *(float4*)(&Bs[kk][n4]) =
                *(const float4*)(W + (size_t)(kc + kk) * D + n4);
        }
        __syncthreads();

#pragma unroll
        for (int kk = 0; kk < 16; kk++) {
            float a[8], b[8];
            *(float4*)(a)     = *(const float4*)(&As[kk][rB]);
            *(float4*)(a + 4) = *(const float4*)(&As[kk][rB + 4]);
            *(float4*)(b)     = *(const float4*)(&Bs[kk][cB]);
            *(float4*)(b + 4) = *(const float4*)(&Bs[kk][cB + 4]);
#pragma unroll
            for (int i = 0; i < 8; i++)
#pragma unroll
                for (int j = 0; j < 8; j++)
                    acc[i][j] += a[i] * b[j];
        }
        __syncthreads();
    }

    // epilogue: bias + (optional) relu + store
#pragma unroll
    for (int i = 0; i < 8; i++) {
        int grow = row0 + rB + i;
        if (grow >= NN) break;
        float o[8];
#pragma unroll
        for (int j = 0; j < 8; j++) {
            float v = acc[i][j] + bias[cB + j];
            if (doRelu) v = fmaxf(v, 0.f);
            o[j] = v;
        }
        *(float4*)(hout + (size_t)grow * D + cB)     = *(float4*)(o);
        *(float4*)(hout + (size_t)grow * D + cB + 4) = *(float4*)(o + 4);
    }
}

// ---------------- pooling: one block per graph over its contiguous range ----
// batch sorted => nodes of graph g are [g_gstart[g], g_gstart[g+1]).
// 128 threads; thread n accumulates feature dim n of agg3 and h2.
__global__ __launch_bounds__(128) void k_pool() {
    int g = blockIdx.x;
    int n = threadIdx.x;
    int beg = g_gstart[g], end = g_gstart[g + 1];
    float sa = 0.f, sh = 0.f;
    for (int node = beg; node < end; node++) {
        sa += g_agg[(size_t)node * D + n];
        sh += g_h2[(size_t)node * D + n];
    }
    int cnt = end - beg;
    float cinv = 1.0f / (float)max(cnt, 1);
    g_pool[g * 2 * D + n]     = sa * cinv;
    g_pool[g * 2 * D + D + n] = sh * cinv;
}

// ---------------- final head: layer3 (pooled) + linear ----------------
__global__ void k_final(const float* __restrict__ W3rel,
                        const float* __restrict__ W3root,
                        const float* __restrict__ b3,
                        const float* __restrict__ Wl,
                        const float* __restrict__ bl,
                        float* __restrict__ out)
{
    __shared__ float pa[128], ph[128], t[128];
    int g = blockIdx.x, n = threadIdx.x;
    int cnt = g_gstart[g + 1] - g_gstart[g];
    float bsel = (cnt > 0) ? 1.0f : 0.0f;   // empty graph => pooled h3 == 0
    pa[n] = g_pool[g * 2 * D + n];
    ph[n] = g_pool[g * 2 * D + D + n];
    __syncthreads();
    float acc = b3[n] * bsel;
#pragma unroll 8
    for (int k = 0; k < 128; k++)
        acc += pa[k] * W3rel[k * D + n] + ph[k] * W3root[k * D + n];
    t[n] = acc;
    __syncthreads();
    if (n < DOUT) {
        float o = bl[n];
#pragma unroll 8
        for (int k = 0; k < 128; k++)
            o += t[k] * Wl[k * DOUT + n];
        out[g * DOUT + n] = o;
    }
}

// ---------------- launcher ----------------
extern "C" void kernel_launch(void* const* d_in, const int* in_sizes, int n_in,
                              void* d_out, int out_size) {
    const float* x      = (const float*)d_in[0];
    const int*   ei     = (const int*)d_in[1];    // int64 normalized to int32 by harness
    const int*   batch  = (const int*)d_in[2];    // int64 normalized to int32 by harness
    const float* W1rel  = (const float*)d_in[3];
    const float* b1     = (const float*)d_in[4];
    const float* W1root = (const float*)d_in[5];
    const float* W2rel  = (const float*)d_in[6];
    const float* b2     = (const float*)d_in[7];
    const float* W2root = (const float*)d_in[8];
    const float* W3rel  = (const float*)d_in[9];
    const float* b3     = (const float*)d_in[10];
    const float* W3root = (const float*)d_in[11];
    const float* Wl     = (const float*)d_in[12];
    const float* bl     = (const float*)d_in[13];
    float*       out    = (float*)d_out;

    float *h1, *h2, *agg;
    cudaGetSymbolAddress((void**)&h1, g_h1);
    cudaGetSymbolAddress((void**)&h2, g_h2);
    cudaGetSymbolAddress((void**)&agg, g_agg);

    const int TB = 256;
    int gbN   = (NN + TB - 1) / TB;          // 391
    int gbE   = (NE + TB - 1) / TB;          // 6250
    int gbW   = (NN * 32 + TB - 1) / TB;     // 12500 (warp per node)
    int gbM   = (NN + 127) / 128;            // 782

    k_init<<<gbN, TB>>>();
    k_hist<<<gbE, TB>>>(ei);
    k_scan<<<1, 1024>>>();
    k_fill<<<gbE, TB>>>(ei);
    k_gbounds<<<1, NG + 1>>>(batch);

    // layer 1
    k_agg<<<gbW, TB>>>(x);
    k_gemm<<<gbM, TB>>>(agg, x, W1rel, W1root, b1, h1, 1);
    // layer 2
    k_agg<<<gbW, TB>>>(h1);
    k_gemm<<<gbM, TB>>>(agg, h1, W2rel, W2root, b2, h2, 1);
    // layer 3 aggregation only (GEMM folded into pooled head)
    k_agg<<<gbW, TB>>>(h2);
    k_pool<<<NG, 128>>>();
    k_final<<<NG, 128>>>(W3rel, W3root, b3, Wl, bl, out);
}

// round 5
// speedup vs baseline: 1.0017x; 1.0017x over previous
#include <cuda_runtime.h>
#include <cstdint>

#define NN 100000
#define NE 1600000
#define NG 256
#define D  128
#define DOUT 64

// ---------------- scratch (static device globals; no allocs) ----------------
__device__ __align__(16) float g_h1[(size_t)NN * D];
__device__ __align__(16) float g_h2[(size_t)NN * D];
__device__ __align__(16) float g_agg[(size_t)NN * D];
__device__ __align__(16) int   g_rowoff[NN + 1];
__device__ __align__(16) int   g_cursor[NN];
__device__ __align__(16) int   g_count[NN];
__device__ __align__(16) int   g_csr[NE];
__device__ __align__(16) float g_deginv[NN];
__device__ __align__(16) float g_pool[NG * 2 * D];   // [g][0:128]=aggmean, [128:256]=hmean
__device__ __align__(16) int   g_gstart[NG + 1];

// ---------------- init: zero edge counters ----------------
__global__ void k_init() {
    int i = blockIdx.x * blockDim.x + threadIdx.x;
    if (i < NN) g_count[i] = 0;
}

// ---------------- in-degree histogram over dst ----------------
__global__ void k_hist(const int* __restrict__ ei) {
    int e = blockIdx.x * blockDim.x + threadIdx.x;
    if (e < NE) {
        int d = ei[NE + e];
        atomicAdd(&g_count[d], 1);
    }
}

// ---------------- single-block exclusive scan -> rowoff/cursor/deginv -------
__global__ void k_scan() {
    const int CH = 98;                 // 1024*98 >= 100000
    __shared__ int sc[1024];
    int t = threadIdx.x;
    int base = t * CH;
    int s = 0;
    for (int i = 0; i < CH; i++) {
        int idx = base + i;
        if (idx < NN) s += g_count[idx];
    }
    sc[t] = s;
    __syncthreads();
    for (int off = 1; off < 1024; off <<= 1) {
        int v = (t >= off) ? sc[t - off] : 0;
        __syncthreads();
        sc[t] += v;
        __syncthreads();
    }
    int run = sc[t] - s;               // exclusive prefix
    for (int i = 0; i < CH; i++) {
        int idx = base + i;
        if (idx < NN) {
            int c = g_count[idx];
            g_rowoff[idx] = run;
            g_cursor[idx] = run;
            g_deginv[idx] = 1.0f / (float)max(c, 1);
            run += c;
        }
    }
    if (t == 1023) g_rowoff[NN] = sc[1023];
}

// ---------------- CSR fill (src list grouped by dst) ----------------
__global__ void k_fill(const int* __restrict__ ei) {
    int e = blockIdx.x * blockDim.x + threadIdx.x;
    if (e < NE) {
        int s = ei[e];
        int d = ei[NE + e];
        int pos = atomicAdd(&g_cursor[d], 1);
        g_csr[pos] = s;
    }
}

// ---------------- graph boundaries: batch is sorted ----------------
__global__ void k_gbounds(const int* __restrict__ batch) {
    int g = threadIdx.x;
    if (g > NG) return;
    int lo = 0, hi = NN;
    while (lo < hi) {
        int mid = (lo + hi) >> 1;
        if (batch[mid] < g) lo = mid + 1; else hi = mid;
    }
    g_gstart[g] = lo;
}

// ---------------- gather-mean aggregation: one warp per node ----------------
__global__ void k_agg(const float* __restrict__ hin) {
    int node = (blockIdx.x * blockDim.x + threadIdx.x) >> 5;
    if (node >= NN) return;
    int lane = threadIdx.x & 31;
    int beg = g_rowoff[node], end = g_rowoff[node + 1];
    float4 acc = make_float4(0.f, 0.f, 0.f, 0.f);
    for (int e = beg; e < end; e++) {
        int s = g_csr[e];
        float4 v = *(const float4*)(hin + (size_t)s * D + lane * 4);
        acc.x += v.x; acc.y += v.y; acc.z += v.z; acc.w += v.w;
    }
    float sc = g_deginv[node];
    acc.x *= sc; acc.y *= sc; acc.z *= sc; acc.w *= sc;
    *(float4*)(g_agg + (size_t)node * D + lane * 4) = acc;
}

// ---------------- fused GEMM: hout = act(agg@Wrel + hin@Wroot + b) ----------
// 128x128 block tile, K=256, BK=16, 256 threads, 8x8 microtile computed as
// 4x8 packed f32x2 pairs (pairs along the row axis -> a-pairs free from smem;
// b broadcast into (b,b) pairs). fma.rn.f32x2 doubles fp32 FMA rate on B300.
__global__ __launch_bounds__(256) void k_gemm(
    const float* __restrict__ A0,    // agg (scaled), k in [0,128)
    const float* __restrict__ A1,    // hin,          k in [128,256)
    const float* __restrict__ Wrel,
    const float* __restrict__ Wroot,
    const float* __restrict__ bias,
    float* __restrict__ hout,
    int doRelu)
{
    __shared__ float As[16][132];    // [k][row], padded (row start 132*4=528B, 16B-aligned)
    __shared__ float Bs[16][128];    // [k][n]
    int row0 = blockIdx.x * 128;
    int tid = threadIdx.x;
    int tr = tid >> 4, tc = tid & 15;
    int rB = tr * 8, cB = tc * 8;

    // packed accumulators: acc2[p][j] = (acc[2p][j], acc[2p+1][j])
    unsigned long long acc2[4][8];
#pragma unroll
    for (int p = 0; p < 4; p++)
#pragma unroll
        for (int j = 0; j < 8; j++) acc2[p][j] = 0ull;

#pragma unroll 1
    for (int kt = 0; kt < 16; kt++) {
        int k0 = kt * 16;
        const float* src = (k0 < 128) ? A0 : A1;
        const float* W   = (k0 < 128) ? Wrel : Wroot;
        int kc = k0 & 127;

        // load A tile (128 rows x 16 k), store transposed into smem
#pragma unroll
        for (int i = 0; i < 2; i++) {
            int slot = tid * 2 + i;                 // 0..511
            int r = slot >> 2;
            int c4 = (slot & 3) * 4;
            float4 v = make_float4(0.f, 0.f, 0.f, 0.f);
            int grow = row0 + r;
            if (grow < NN)
                v = *(const float4*)(src + (size_t)grow * D + kc + c4);
            As[c4 + 0][r] = v.x;
            As[c4 + 1][r] = v.y;
            As[c4 + 2][r] = v.z;
            As[c4 + 3][r] = v.w;
        }
        // load B tile (16 k x 128 n)
#pragma unroll
        for (int i = 0; i < 2; i++) {
            int slot = tid * 2 + i;                 // 0..511
            int kk = slot >> 5;
            int n4 = (slot & 31) * 4;
            *(float4*)(&Bs[kk][n4]) =
                *(const float4*)(W + (size_t)(kc + kk) * D + n4);
        }
        __syncthreads();

#pragma unroll
        for (int kk = 0; kk < 16; kk++) {
            // a pairs straight from smem (16B aligned)
            ulonglong2 a01 = *(const ulonglong2*)(&As[kk][rB]);
            ulonglong2 a23 = *(const ulonglong2*)(&As[kk][rB + 4]);
            unsigned long long ap[4] = {a01.x, a01.y, a23.x, a23.y};
            // b scalars -> broadcast pairs
            float4 b0 = *(const float4*)(&Bs[kk][cB]);
            float4 b1 = *(const float4*)(&Bs[kk][cB + 4]);
            float bv[8] = {b0.x, b0.y, b0.z, b0.w, b1.x, b1.y, b1.z, b1.w};
            unsigned long long bb[8];
#pragma unroll
            for (int j = 0; j < 8; j++)
                asm("mov.b64 %0, {%1, %1};" : "=l"(bb[j]) : "f"(bv[j]));
#pragma unroll
            for (int p = 0; p < 4; p++)
#pragma unroll
                for (int j = 0; j < 8; j++)
                    asm("fma.rn.f32x2 %0, %1, %2, %0;"
                        : "+l"(acc2[p][j]) : "l"(ap[p]), "l"(bb[j]));
        }
        __syncthreads();
    }

    // epilogue: unpack pairs, bias + (optional) relu + store
#pragma unroll
    for (int p = 0; p < 4; p++) {
        float olo[8], ohi[8];
#pragma unroll
        for (int j = 0; j < 8; j++) {
            float lo, hi;
            asm("mov.b64 {%0, %1}, %2;" : "=f"(lo), "=f"(hi) : "l"(acc2[p][j]));
            lo += bias[cB + j];
            hi += bias[cB + j];
            if (doRelu) { lo = fmaxf(lo, 0.f); hi = fmaxf(hi, 0.f); }
            olo[j] = lo; ohi[j] = hi;
        }
        int rlo = row0 + rB + 2 * p;
        int rhi = rlo + 1;
        if (rlo < NN) {
            *(float4*)(hout + (size_t)rlo * D + cB)     = *(float4*)(olo);
            *(float4*)(hout + (size_t)rlo * D + cB + 4) = *(float4*)(olo + 4);
        }
        if (rhi < NN) {
            *(float4*)(hout + (size_t)rhi * D + cB)     = *(float4*)(ohi);
            *(float4*)(hout + (size_t)rhi * D + cB + 4) = *(float4*)(ohi + 4);
        }
    }
}

// ---------------- pooling: one block per graph over its contiguous range ----
__global__ __launch_bounds__(128) void k_pool() {
    int g = blockIdx.x;
    int n = threadIdx.x;
    int beg = g_gstart[g], end = g_gstart[g + 1];
    float sa = 0.f, sh = 0.f;
    for (int node = beg; node < end; node++) {
        sa += g_agg[(size_t)node * D + n];
        sh += g_h2[(size_t)node * D + n];
    }
    int cnt = end - beg;
    float cinv = 1.0f / (float)max(cnt, 1);
    g_pool[g * 2 * D + n]     = sa * cinv;
    g_pool[g * 2 * D + D + n] = sh * cinv;
}

// ---------------- final head: layer3 (pooled) + linear ----------------
__global__ void k_final(const float* __restrict__ W3rel,
                        const float* __restrict__ W3root,
                        const float* __restrict__ b3,
                        const float* __restrict__ Wl,
                        const float* __restrict__ bl,
                        float* __restrict__ out)
{
    __shared__ float pa[128], ph[128], t[128];
    int g = blockIdx.x, n = threadIdx.x;
    int cnt = g_gstart[g + 1] - g_gstart[g];
    float bsel = (cnt > 0) ? 1.0f : 0.0f;   // empty graph => pooled h3 == 0
    pa[n] = g_pool[g * 2 * D + n];
    ph[n] = g_pool[g * 2 * D + D + n];
    __syncthreads();
    float acc = b3[n] * bsel;
#pragma unroll 8
    for (int k = 0; k < 128; k++)
        acc += pa[k] * W3rel[k * D + n] + ph[k] * W3root[k * D + n];
    t[n] = acc;
    __syncthreads();
    if (n < DOUT) {
        float o = bl[n];
#pragma unroll 8
        for (int k = 0; k < 128; k++)
            o += t[k] * Wl[k * DOUT + n];
        out[g * DOUT + n] = o;
    }
}

// ---------------- launcher ----------------
extern "C" void kernel_launch(void* const* d_in, const int* in_sizes, int n_in,
                              void* d_out, int out_size) {
    const float* x      = (const float*)d_in[0];
    const int*   ei     = (const int*)d_in[1];    // int64 normalized to int32 by harness
    const int*   batch  = (const int*)d_in[2];
    const float* W1rel  = (const float*)d_in[3];
    const float* b1     = (const float*)d_in[4];
    const float* W1root = (const float*)d_in[5];
    const float* W2rel  = (const float*)d_in[6];
    const float* b2     = (const float*)d_in[7];
    const float* W2root = (const float*)d_in[8];
    const float* W3rel  = (const float*)d_in[9];
    const float* b3     = (const float*)d_in[10];
    const float* W3root = (const float*)d_in[11];
    const float* Wl     = (const float*)d_in[12];
    const float* bl     = (const float*)d_in[13];
    float*       out    = (float*)d_out;

    float *h1, *h2, *agg;
    cudaGetSymbolAddress((void**)&h1, g_h1);
    cudaGetSymbolAddress((void**)&h2, g_h2);
    cudaGetSymbolAddress((void**)&agg, g_agg);

    const int TB = 256;
    int gbN   = (NN + TB - 1) / TB;          // 391
    int gbE   = (NE + TB - 1) / TB;          // 6250
    int gbW   = (NN * 32 + TB - 1) / TB;     // 12500 (warp per node)
    int gbM   = (NN + 127) / 128;            // 782

    k_init<<<gbN, TB>>>();
    k_hist<<<gbE, TB>>>(ei);
    k_scan<<<1, 1024>>>();
    k_fill<<<gbE, TB>>>(ei);
    k_gbounds<<<1, NG + 1>>>(batch);

    // layer 1
    k_agg<<<gbW, TB>>>(x);
    k_gemm<<<gbM, TB>>>(agg, x, W1rel, W1root, b1, h1, 1);
    // layer 2
    k_agg<<<gbW, TB>>>(h1);
    k_gemm<<<gbM, TB>>>(agg, h1, W2rel, W2root, b2, h2, 1);
    // layer 3 aggregation only (GEMM folded into pooled head)
    k_agg<<<gbW, TB>>>(h2);
    k_pool<<<NG, 128>>>();
    k_final<<<NG, 128>>>(W3rel, W3root, b3, Wl, bl, out);
}

// round 6
// speedup vs baseline: 1.2318x; 1.2298x over previous
#include <cuda_runtime.h>
#include <cstdint>

#define NN 100000
#define NE 1600000
#define NG 256
#define D  128
#define DOUT 64

// ---------------- scratch (static device globals; no allocs) ----------------
__device__ __align__(16) float g_h1[(size_t)NN * D];
__device__ __align__(16) float g_h2[(size_t)NN * D];
__device__ __align__(16) float g_agg[(size_t)NN * D];
__device__ __align__(16) int   g_rowoff[NN + 1];
__device__ __align__(16) int   g_cursor[NN];
__device__ __align__(16) int   g_count[NN];
__device__ __align__(16) int   g_csr[NE];
__device__ __align__(16) float g_deginv[NN];
__device__ __align__(16) float g_pool[NG * 2 * D];
__device__ __align__(16) int   g_gstart[NG + 1];

// ---------------- init ----------------
__global__ void k_init() {
    int i = blockIdx.x * blockDim.x + threadIdx.x;
    if (i < NN) g_count[i] = 0;
}

// ---------------- in-degree histogram over dst ----------------
__global__ void k_hist(const int* __restrict__ ei) {
    int e = blockIdx.x * blockDim.x + threadIdx.x;
    if (e < NE) {
        int d = ei[NE + e];
        atomicAdd(&g_count[d], 1);
    }
}

// ---------------- single-block exclusive scan ----------------
__global__ void k_scan() {
    const int CH = 98;
    __shared__ int sc[1024];
    int t = threadIdx.x;
    int base = t * CH;
    int s = 0;
    for (int i = 0; i < CH; i++) {
        int idx = base + i;
        if (idx < NN) s += g_count[idx];
    }
    sc[t] = s;
    __syncthreads();
    for (int off = 1; off < 1024; off <<= 1) {
        int v = (t >= off) ? sc[t - off] : 0;
        __syncthreads();
        sc[t] += v;
        __syncthreads();
    }
    int run = sc[t] - s;
    for (int i = 0; i < CH; i++) {
        int idx = base + i;
        if (idx < NN) {
            int c = g_count[idx];
            g_rowoff[idx] = run;
            g_cursor[idx] = run;
            g_deginv[idx] = 1.0f / (float)max(c, 1);
            run += c;
        }
    }
    if (t == 1023) g_rowoff[NN] = sc[1023];
}

// ---------------- CSR fill ----------------
__global__ void k_fill(const int* __restrict__ ei) {
    int e = blockIdx.x * blockDim.x + threadIdx.x;
    if (e < NE) {
        int s = ei[e];
        int d = ei[NE + e];
        int pos = atomicAdd(&g_cursor[d], 1);
        g_csr[pos] = s;
    }
}

// ---------------- graph boundaries (batch sorted) ----------------
__global__ void k_gbounds(const int* __restrict__ batch) {
    int g = threadIdx.x;
    if (g > NG) return;
    int lo = 0, hi = NN;
    while (lo < hi) {
        int mid = (lo + hi) >> 1;
        if (batch[mid] < g) lo = mid + 1; else hi = mid;
    }
    g_gstart[g] = lo;
}

// ---------------- gather-mean aggregation: one warp per node ----------------
__global__ void k_agg(const float* __restrict__ hin) {
    int node = (blockIdx.x * blockDim.x + threadIdx.x) >> 5;
    if (node >= NN) return;
    int lane = threadIdx.x & 31;
    int beg = g_rowoff[node], end = g_rowoff[node + 1];
    float4 acc = make_float4(0.f, 0.f, 0.f, 0.f);
    for (int e = beg; e < end; e++) {
        int s = g_csr[e];
        float4 v = *(const float4*)(hin + (size_t)s * D + lane * 4);
        acc.x += v.x; acc.y += v.y; acc.z += v.z; acc.w += v.w;
    }
    float sc = g_deginv[node];
    acc.x *= sc; acc.y *= sc; acc.z *= sc; acc.w *= sc;
    *(float4*)(g_agg + (size_t)node * D + lane * 4) = acc;
}

// ---------------- tf32 round-to-nearest helper ----------------
__device__ __forceinline__ float tf32r(float x) {
    uint32_t u;
    asm("cvt.rna.tf32.f32 %0, %1;" : "=r"(u) : "f"(x));
    return __uint_as_float(u);
}

// ---------------- fused GEMM (tf32 tensor cores) ----------------
// hout = act(agg@Wrel + hin@Wroot + b); 128x128 block tile, K=256, BK=16.
// 8 warps in 2(m)x4(n) grid; warp tile 64x32 via mma.m16n8k8.tf32 (4x4 frags).
__global__ __launch_bounds__(256) void k_gemm(
    const float* __restrict__ A0,    // agg, k in [0,128)
    const float* __restrict__ A1,    // hin, k in [128,256)
    const float* __restrict__ Wrel,
    const float* __restrict__ Wroot,
    const float* __restrict__ bias,
    float* __restrict__ hout,
    int doRelu)
{
    __shared__ float As[16][132];    // [k][row], tf32-rounded
    __shared__ float Bs[16][132];    // [k][n],  tf32-rounded
    int row0 = blockIdx.x * 128;
    int tid  = threadIdx.x;
    int warp = tid >> 5, lane = tid & 31;
    int wm = warp >> 2;              // 0..1 -> row offset wm*64
    int wn = warp & 3;               // 0..3 -> col offset wn*32
    int r  = lane >> 2;              // 0..7
    int cq = lane & 3;               // 0..3

    float acc[4][4][4];
#pragma unroll
    for (int mi = 0; mi < 4; mi++)
#pragma unroll
        for (int ni = 0; ni < 4; ni++)
#pragma unroll
            for (int q = 0; q < 4; q++) acc[mi][ni][q] = 0.f;

#pragma unroll 1
    for (int kt = 0; kt < 16; kt++) {
        int k0 = kt * 16;
        const float* src = (k0 < 128) ? A0 : A1;
        const float* W   = (k0 < 128) ? Wrel : Wroot;
        int kc = k0 & 127;

        // stage A tile (128 rows x 16 k), transposed, tf32-rounded
#pragma unroll
        for (int i = 0; i < 2; i++) {
            int slot = tid * 2 + i;                 // 0..511
            int rr = slot >> 2;
            int c4 = (slot & 3) * 4;
            float4 v = make_float4(0.f, 0.f, 0.f, 0.f);
            int grow = row0 + rr;
            if (grow < NN)
                v = *(const float4*)(src + (size_t)grow * D + kc + c4);
            As[c4 + 0][rr] = tf32r(v.x);
            As[c4 + 1][rr] = tf32r(v.y);
            As[c4 + 2][rr] = tf32r(v.z);
            As[c4 + 3][rr] = tf32r(v.w);
        }
        // stage B tile (16 k x 128 n), tf32-rounded
#pragma unroll
        for (int i = 0; i < 2; i++) {
            int slot = tid * 2 + i;
            int kk = slot >> 5;
            int n4 = (slot & 31) * 4;
            float4 v = *(const float4*)(W + (size_t)(kc + kk) * D + n4);
            float4 cv = make_float4(tf32r(v.x), tf32r(v.y), tf32r(v.z), tf32r(v.w));
            *(float4*)(&Bs[kk][n4]) = cv;
        }
        __syncthreads();

#pragma unroll
        for (int ks = 0; ks < 16; ks += 8) {
            // B fragments: b0 at (k=cq, n=r), b1 at (k=cq+4, n=r)
            uint32_t bf[4][2];
#pragma unroll
            for (int ni = 0; ni < 4; ni++) {
                int n = wn * 32 + ni * 8 + r;
                bf[ni][0] = __float_as_uint(Bs[ks + cq][n]);
                bf[ni][1] = __float_as_uint(Bs[ks + cq + 4][n]);
            }
#pragma unroll
            for (int mi = 0; mi < 4; mi++) {
                int row = wm * 64 + mi * 16 + r;
                uint32_t a0 = __float_as_uint(As[ks + cq][row]);
                uint32_t a1 = __float_as_uint(As[ks + cq][row + 8]);
                uint32_t a2 = __float_as_uint(As[ks + cq + 4][row]);
                uint32_t a3 = __float_as_uint(As[ks + cq + 4][row + 8]);
#pragma unroll
                for (int ni = 0; ni < 4; ni++) {
                    asm volatile(
                        "mma.sync.aligned.m16n8k8.row.col.f32.tf32.tf32.f32 "
                        "{%0,%1,%2,%3}, {%4,%5,%6,%7}, {%8,%9}, {%0,%1,%2,%3};"
                        : "+f"(acc[mi][ni][0]), "+f"(acc[mi][ni][1]),
                          "+f"(acc[mi][ni][2]), "+f"(acc[mi][ni][3])
                        : "r"(a0), "r"(a1), "r"(a2), "r"(a3),
                          "r"(bf[ni][0]), "r"(bf[ni][1]));
                }
            }
        }
        __syncthreads();
    }

    // epilogue: bias + relu + store
#pragma unroll
    for (int mi = 0; mi < 4; mi++) {
        int r0g = row0 + wm * 64 + mi * 16 + r;
        int r1g = r0g + 8;
#pragma unroll
        for (int ni = 0; ni < 4; ni++) {
            int col = wn * 32 + ni * 8 + 2 * cq;
            float bz0 = bias[col], bz1 = bias[col + 1];
            float v0 = acc[mi][ni][0] + bz0, v1 = acc[mi][ni][1] + bz1;
            float v2 = acc[mi][ni][2] + bz0, v3 = acc[mi][ni][3] + bz1;
            if (doRelu) {
                v0 = fmaxf(v0, 0.f); v1 = fmaxf(v1, 0.f);
                v2 = fmaxf(v2, 0.f); v3 = fmaxf(v3, 0.f);
            }
            if (r0g < NN) *(float2*)(hout + (size_t)r0g * D + col) = make_float2(v0, v1);
            if (r1g < NN) *(float2*)(hout + (size_t)r1g * D + col) = make_float2(v2, v3);
        }
    }
}

// ---------------- pooling: one block per graph over contiguous range ----
__global__ __launch_bounds__(128) void k_pool() {
    int g = blockIdx.x;
    int n = threadIdx.x;
    int beg = g_gstart[g], end = g_gstart[g + 1];
    float sa = 0.f, sh = 0.f;
    for (int node = beg; node < end; node++) {
        sa += g_agg[(size_t)node * D + n];
        sh += g_h2[(size_t)node * D + n];
    }
    int cnt = end - beg;
    float cinv = 1.0f / (float)max(cnt, 1);
    g_pool[g * 2 * D + n]     = sa * cinv;
    g_pool[g * 2 * D + D + n] = sh * cinv;
}

// ---------------- final head: layer3 (pooled) + linear, fp32 ----------------
__global__ void k_final(const float* __restrict__ W3rel,
                        const float* __restrict__ W3root,
                        const float* __restrict__ b3,
                        const float* __restrict__ Wl,
                        const float* __restrict__ bl,
                        float* __restrict__ out)
{
    __shared__ float pa[128], ph[128], t[128];
    int g = blockIdx.x, n = threadIdx.x;
    int cnt = g_gstart[g + 1] - g_gstart[g];
    float bsel = (cnt > 0) ? 1.0f : 0.0f;
    pa[n] = g_pool[g * 2 * D + n];
    ph[n] = g_pool[g * 2 * D + D + n];
    __syncthreads();
    float acc = b3[n] * bsel;
#pragma unroll 8
    for (int k = 0; k < 128; k++)
        acc += pa[k] * W3rel[k * D + n] + ph[k] * W3root[k * D + n];
    t[n] = acc;
    __syncthreads();
    if (n < DOUT) {
        float o = bl[n];
#pragma unroll 8
        for (int k = 0; k < 128; k++)
            o += t[k] * Wl[k * DOUT + n];
        out[g * DOUT + n] = o;
    }
}

// ---------------- launcher ----------------
extern "C" void kernel_launch(void* const* d_in, const int* in_sizes, int n_in,
                              void* d_out, int out_size) {
    const float* x      = (const float*)d_in[0];
    const int*   ei     = (const int*)d_in[1];
    const int*   batch  = (const int*)d_in[2];
    const float* W1rel  = (const float*)d_in[3];
    const float* b1     = (const float*)d_in[4];
    const float* W1root = (const float*)d_in[5];
    const float* W2rel  = (const float*)d_in[6];
    const float* b2     = (const float*)d_in[7];
    const float* W2root = (const float*)d_in[8];
    const float* W3rel  = (const float*)d_in[9];
    const float* b3     = (const float*)d_in[10];
    const float* W3root = (const float*)d_in[11];
    const float* Wl     = (const float*)d_in[12];
    const float* bl     = (const float*)d_in[13];
    float*       out    = (float*)d_out;

    float *h1, *h2, *agg;
    cudaGetSymbolAddress((void**)&h1, g_h1);
    cudaGetSymbolAddress((void**)&h2, g_h2);
    cudaGetSymbolAddress((void**)&agg, g_agg);

    const int TB = 256;
    int gbN   = (NN + TB - 1) / TB;
    int gbE   = (NE + TB - 1) / TB;
    int gbW   = (NN * 32 + TB - 1) / TB;
    int gbM   = (NN + 127) / 128;

    k_init<<<gbN, TB>>>();
    k_hist<<<gbE, TB>>>(ei);
    k_scan<<<1, 1024>>>();
    k_fill<<<gbE, TB>>>(ei);
    k_gbounds<<<1, NG + 1>>>(batch);

    k_agg<<<gbW, TB>>>(x);
    k_gemm<<<gbM, TB>>>(agg, x, W1rel, W1root, b1, h1, 1);
    k_agg<<<gbW, TB>>>(h1);
    k_gemm<<<gbM, TB>>>(agg, h1, W2rel, W2root, b2, h2, 1);
    k_agg<<<gbW, TB>>>(h2);
    k_pool<<<NG, 128>>>();
    k_final<<<NG, 128>>>(W3rel, W3root, b3, Wl, bl, out);
}